// round 2
// baseline (speedup 1.0000x reference)
#include <cuda_runtime.h>
#include <math.h>

#define NLVL 4
#define NHEAD 8
#define NPNT 4
#define CDIM 256
#define HDIM 32
#define DFFD 1024
#define NLAYER 6
#define BSZ 2
#define STOT 20197
#define MTOT (BSZ * STOT)   // 40394

// ---------------- scratch buffers (device globals; no allocation) -----------
__device__ float g_q[MTOT * CDIM];
__device__ float g_val[MTOT * CDIM];
__device__ float g_off[MTOT * 256];
__device__ float g_att[MTOT * 128];
__device__ float g_samp[MTOT * CDIM];
__device__ float g_proj[MTOT * CDIM];
__device__ float g_xa[MTOT * CDIM];
__device__ float g_ff[MTOT * DFFD];
__device__ float g_x[MTOT * CDIM];

__constant__ int c_H[NLVL]     = {100, 50, 25, 13};
__constant__ int c_W[NLVL]     = {152, 76, 38, 19};
__constant__ int c_start[NLVL] = {0, 15200, 19000, 19950};

// ---------------- elementwise add: q = x + pos ------------------------------
__global__ void add_kernel(const float* __restrict__ a, const float* __restrict__ b,
                           float* __restrict__ o, int n4) {
    int i = blockIdx.x * blockDim.x + threadIdx.x;
    if (i < n4) {
        float4 x = ((const float4*)a)[i];
        float4 y = ((const float4*)b)[i];
        float4 r;
        r.x = x.x + y.x; r.y = x.y + y.y; r.z = x.z + y.z; r.w = x.w + y.w;
        ((float4*)o)[i] = r;
    }
}

// ---------------- classic SGEMM: C = A[MxK] * W[KxN] + bias (opt ReLU) ------
// BM=BN=128, BK=8, 256 threads, 8x8 per-thread tile. N must be mult of 128,
// K mult of 8. M edge guarded.
template <int RELU>
__global__ __launch_bounds__(256, 2) void sgemm_bias(
    const float* __restrict__ A, const float* __restrict__ W,
    const float* __restrict__ bias, float* __restrict__ Cout,
    int M, int K, int N) {
    __shared__ float As[8][128];
    __shared__ float Bs[8][128];

    const int tid = threadIdx.x;
    const int bm = blockIdx.y * 128;
    const int bn = blockIdx.x * 128;
    const int tx = tid & 15;        // 0..15 -> col group
    const int ty = tid >> 4;        // 0..15 -> row group

    const int arow = tid >> 1;          // 0..127
    const int acol = (tid & 1) * 4;     // 0 or 4
    const int brow = tid >> 5;          // 0..7
    const int bcol = (tid & 31) * 4;    // 0..124

    float acc[8][8];
#pragma unroll
    for (int i = 0; i < 8; i++)
#pragma unroll
        for (int j = 0; j < 8; j++) acc[i][j] = 0.0f;

    for (int k0 = 0; k0 < K; k0 += 8) {
        // load A tile (transposed into smem)
        int gm = bm + arow;
        float4 av = make_float4(0.f, 0.f, 0.f, 0.f);
        if (gm < M) av = *(const float4*)(A + (size_t)gm * K + k0 + acol);
        As[acol + 0][arow] = av.x;
        As[acol + 1][arow] = av.y;
        As[acol + 2][arow] = av.z;
        As[acol + 3][arow] = av.w;
        // load B tile
        float4 bv = *(const float4*)(W + (size_t)(k0 + brow) * N + bn + bcol);
        *(float4*)&Bs[brow][bcol] = bv;
        __syncthreads();

#pragma unroll
        for (int k = 0; k < 8; k++) {
            float a[8], b[8];
            *(float4*)&a[0] = *(float4*)&As[k][ty * 8];
            *(float4*)&a[4] = *(float4*)&As[k][ty * 8 + 4];
            *(float4*)&b[0] = *(float4*)&Bs[k][tx * 8];
            *(float4*)&b[4] = *(float4*)&Bs[k][tx * 8 + 4];
#pragma unroll
            for (int i = 0; i < 8; i++)
#pragma unroll
                for (int j = 0; j < 8; j++) acc[i][j] += a[i] * b[j];
        }
        __syncthreads();
    }

#pragma unroll
    for (int i = 0; i < 8; i++) {
        int gm = bm + ty * 8 + i;
        if (gm >= M) continue;
#pragma unroll
        for (int j = 0; j < 8; j += 4) {
            int gn = bn + tx * 8 + j;
            float4 v;
            v.x = acc[i][j + 0] + __ldg(bias + gn + 0);
            v.y = acc[i][j + 1] + __ldg(bias + gn + 1);
            v.z = acc[i][j + 2] + __ldg(bias + gn + 2);
            v.w = acc[i][j + 3] + __ldg(bias + gn + 3);
            if (RELU) {
                v.x = fmaxf(v.x, 0.f); v.y = fmaxf(v.y, 0.f);
                v.z = fmaxf(v.z, 0.f); v.w = fmaxf(v.w, 0.f);
            }
            *(float4*)(Cout + (size_t)gm * N + gn) = v;
        }
    }
}

// ---------------- residual + LayerNorm: out = LN(resid + delta) -------------
// one warp per row (C=256 -> 8 per lane)
__global__ void ln_kernel(const float* __restrict__ resid, const float* __restrict__ delta,
                          const float* __restrict__ gamma, const float* __restrict__ beta,
                          float* __restrict__ out, int Mrows) {
    int warp = threadIdx.x >> 5;
    int lane = threadIdx.x & 31;
    int row = blockIdx.x * 8 + warp;
    if (row >= Mrows) return;
    const float* r = resid + (size_t)row * CDIM;
    const float* d = delta + (size_t)row * CDIM;
    float v[8];
    float s = 0.f;
#pragma unroll
    for (int i = 0; i < 8; i++) {
        int c = lane + i * 32;
        v[i] = r[c] + d[c];
        s += v[i];
    }
#pragma unroll
    for (int o = 16; o > 0; o >>= 1) s += __shfl_xor_sync(0xffffffffu, s, o);
    float mean = s * (1.0f / 256.0f);
    float vs = 0.f;
#pragma unroll
    for (int i = 0; i < 8; i++) {
        float t = v[i] - mean;
        vs += t * t;
    }
#pragma unroll
    for (int o = 16; o > 0; o >>= 1) vs += __shfl_xor_sync(0xffffffffu, vs, o);
    float inv = rsqrtf(vs * (1.0f / 256.0f) + 1e-5f);
    float* op = out + (size_t)row * CDIM;
#pragma unroll
    for (int i = 0; i < 8; i++) {
        int c = lane + i * 32;
        op[c] = (v[i] - mean) * inv * gamma[c] + beta[c];
    }
}

// ---------------- MS deformable attention sampling --------------------------
// one warp per (b, s, h); lane = channel within head (HD=32).
// softmax over the 16 attention logits fused (computed redundantly per lane).
__global__ void msda_kernel(const float* __restrict__ val, const float* __restrict__ off,
                            const float* __restrict__ attl, float* __restrict__ out) {
    int gw = blockIdx.x * 8 + (threadIdx.x >> 5);
    int lane = threadIdx.x & 31;
    if (gw >= BSZ * STOT * NHEAD) return;
    int h = gw % NHEAD;
    int bs = gw / NHEAD;       // b*S + s
    int s = bs % STOT;
    int b = bs / STOT;

    // reference point: pixel center of this query's own level
    int rl;
    if (s < 15200) rl = 0;
    else if (s < 19000) rl = 1;
    else if (s < 19950) rl = 2;
    else rl = 3;
    int rs = s - c_start[rl];
    int rW = c_W[rl];
    float refx = ((rs % rW) + 0.5f) / (float)rW;
    float refy = ((rs / rW) + 0.5f) / (float)c_H[rl];

    // softmax over 16 logits (layout: h*16 + l*4 + p)
    const float* ap = attl + (size_t)bs * 128 + h * 16;
    float w[16];
    float mx = -1e30f;
#pragma unroll
    for (int i = 0; i < 16; i++) {
        w[i] = __ldg(ap + i);
        mx = fmaxf(mx, w[i]);
    }
    float ssum = 0.f;
#pragma unroll
    for (int i = 0; i < 16; i++) {
        w[i] = __expf(w[i] - mx);
        ssum += w[i];
    }
    float sinv = 1.0f / ssum;

    const float* op = off + (size_t)bs * 256 + h * 32;  // 16 (x,y) pairs
    float acc = 0.f;
#pragma unroll
    for (int l = 0; l < NLVL; l++) {
        const int Hl = c_H[l], Wl = c_W[l];
        const float* vbase = val + ((size_t)b * STOT + c_start[l]) * CDIM + h * HDIM + lane;
#pragma unroll
        for (int p = 0; p < NPNT; p++) {
            float ox = __ldg(op + (l * 4 + p) * 2 + 0);
            float oy = __ldg(op + (l * 4 + p) * 2 + 1);
            // loc = ref + off/ (W,H); pix = loc*size - 0.5  -> ref*size + off - 0.5
            float lx = refx * (float)Wl + ox - 0.5f;
            float ly = refy * (float)Hl + oy - 0.5f;
            float x0f = floorf(lx), y0f = floorf(ly);
            float fx = lx - x0f, fy = ly - y0f;
            int x0 = (int)x0f, y0 = (int)y0f;
            float aw = w[l * 4 + p] * sinv;
#pragma unroll
            for (int dy = 0; dy < 2; dy++) {
#pragma unroll
                for (int dx = 0; dx < 2; dx++) {
                    int xi = x0 + dx, yi = y0 + dy;
                    if (xi >= 0 && xi < Wl && yi >= 0 && yi < Hl) {
                        float cw = (dx ? fx : 1.f - fx) * (dy ? fy : 1.f - fy) * aw;
                        acc += __ldg(vbase + (size_t)(yi * Wl + xi) * CDIM) * cw;
                    }
                }
            }
        }
    }
    out[(size_t)bs * CDIM + h * HDIM + lane] = acc;
}

// ---------------- host orchestration ----------------------------------------
extern "C" void kernel_launch(void* const* d_in, const int* in_sizes, int n_in,
                              void* d_out, int out_size) {
    const float* src  = (const float*)d_in[0];
    const float* pos  = (const float*)d_in[1];
    const float* Woff = (const float*)d_in[2];
    const float* boff = (const float*)d_in[3];
    const float* Watt = (const float*)d_in[4];
    const float* batt = (const float*)d_in[5];
    const float* Wval = (const float*)d_in[6];
    const float* bval = (const float*)d_in[7];
    const float* Wout = (const float*)d_in[8];
    const float* bout = (const float*)d_in[9];
    const float* W1   = (const float*)d_in[10];
    const float* b1   = (const float*)d_in[11];
    const float* W2   = (const float*)d_in[12];
    const float* b2   = (const float*)d_in[13];
    const float* g1   = (const float*)d_in[14];
    const float* be1  = (const float*)d_in[15];
    const float* g2   = (const float*)d_in[16];
    const float* be2  = (const float*)d_in[17];

    float *qp, *valp, *offp, *attp, *sampp, *projp, *xap, *ffp, *gxp;
    cudaGetSymbolAddress((void**)&qp, g_q);
    cudaGetSymbolAddress((void**)&valp, g_val);
    cudaGetSymbolAddress((void**)&offp, g_off);
    cudaGetSymbolAddress((void**)&attp, g_att);
    cudaGetSymbolAddress((void**)&sampp, g_samp);
    cudaGetSymbolAddress((void**)&projp, g_proj);
    cudaGetSymbolAddress((void**)&xap, g_xa);
    cudaGetSymbolAddress((void**)&ffp, g_ff);
    cudaGetSymbolAddress((void**)&gxp, g_x);

    const int M = MTOT;
    const int gy = (M + 127) / 128;          // 316
    const int lnBlocks = (M + 7) / 8;        // 5050
    const int addN4 = M * CDIM / 4;
    const int addBlocks = (addN4 + 255) / 256;
    const int msdaBlocks = (BSZ * STOT * NHEAD + 7) / 8;  // 40394

    const float* x = src;
    for (int l = 0; l < NLAYER; l++) {
        const float* Woff_l = Woff + (size_t)l * CDIM * 256;
        const float* boff_l = boff + (size_t)l * 256;
        const float* Watt_l = Watt + (size_t)l * CDIM * 128;
        const float* batt_l = batt + (size_t)l * 128;
        const float* Wval_l = Wval + (size_t)l * CDIM * CDIM;
        const float* bval_l = bval + (size_t)l * CDIM;
        const float* Wout_l = Wout + (size_t)l * CDIM * CDIM;
        const float* bout_l = bout + (size_t)l * CDIM;
        const float* W1_l = W1 + (size_t)l * CDIM * DFFD;
        const float* b1_l = b1 + (size_t)l * DFFD;
        const float* W2_l = W2 + (size_t)l * DFFD * CDIM;
        const float* b2_l = b2 + (size_t)l * CDIM;
        const float* g1_l = g1 + (size_t)l * CDIM;
        const float* be1_l = be1 + (size_t)l * CDIM;
        const float* g2_l = g2 + (size_t)l * CDIM;
        const float* be2_l = be2 + (size_t)l * CDIM;

        // q = x + pos
        add_kernel<<<addBlocks, 256>>>(x, pos, qp, addN4);
        // value / offsets / attention logits
        sgemm_bias<0><<<dim3(2, gy), 256>>>(x, Wval_l, bval_l, valp, M, 256, 256);
        sgemm_bias<0><<<dim3(2, gy), 256>>>(qp, Woff_l, boff_l, offp, M, 256, 256);
        sgemm_bias<0><<<dim3(1, gy), 256>>>(qp, Watt_l, batt_l, attp, M, 256, 128);
        // deformable sampling (softmax fused)
        msda_kernel<<<msdaBlocks, 256>>>(valp, offp, attp, sampp);
        // output projection
        sgemm_bias<0><<<dim3(2, gy), 256>>>(sampp, Wout_l, bout_l, projp, M, 256, 256);
        // x1 = LN(x + proj)
        ln_kernel<<<lnBlocks, 256>>>(x, projp, g1_l, be1_l, xap, M);
        // FFN
        sgemm_bias<1><<<dim3(8, gy), 256>>>(xap, W1_l, b1_l, ffp, M, 256, 1024);
        sgemm_bias<0><<<dim3(2, gy), 256>>>(ffp, W2_l, b2_l, projp, M, 1024, 256);
        // x = LN(x1 + ff)
        float* xout = (l == NLAYER - 1) ? (float*)d_out : gxp;
        ln_kernel<<<lnBlocks, 256>>>(xap, projp, g2_l, be2_l, xout, M);
        x = gxp;
    }
}

// round 3
// speedup vs baseline: 1.2620x; 1.2620x over previous
#include <cuda_runtime.h>
#include <math.h>
#include <mma.h>

using namespace nvcuda;

#define NLVL 4
#define NHEAD 8
#define NPNT 4
#define CDIM 256
#define HDIM 32
#define DFFD 1024
#define NLAYER 6
#define BSZ 2
#define STOT 20197
#define MTOT (BSZ * STOT)   // 40394

// ---------------- scratch buffers (device globals; no allocation) -----------
__device__ float g_q[MTOT * CDIM];
__device__ float g_val[MTOT * CDIM];
__device__ float g_off[MTOT * 256];
__device__ float g_att[MTOT * 128];
__device__ float g_samp[MTOT * CDIM];
__device__ float g_proj[MTOT * CDIM];
__device__ float g_xa[MTOT * CDIM];
__device__ float g_ff[MTOT * DFFD];
__device__ float g_x[MTOT * CDIM];

__constant__ int c_H[NLVL]     = {100, 50, 25, 13};
__constant__ int c_W[NLVL]     = {152, 76, 38, 19};
__constant__ int c_start[NLVL] = {0, 15200, 19000, 19950};

// ---------------- elementwise add: q = x + pos ------------------------------
__global__ void add_kernel(const float* __restrict__ a, const float* __restrict__ b,
                           float* __restrict__ o, int n4) {
    int i = blockIdx.x * blockDim.x + threadIdx.x;
    if (i < n4) {
        float4 x = ((const float4*)a)[i];
        float4 y = ((const float4*)b)[i];
        float4 r;
        r.x = x.x + y.x; r.y = x.y + y.y; r.z = x.z + y.z; r.w = x.w + y.w;
        ((float4*)o)[i] = r;
    }
}

// ---------------- tf32 tensor-core GEMM: C = A[MxK]*W[KxN] + bias (opt ReLU)
// BM=BN=128, BK=32, 256 threads (8 warps, 4x2), warp tile 32x64 (2x4 wmma
// m16n16k8 tiles). cp.async double-buffered smem. N mult of 128, K mult of 32.
// M edge: zero-filled loads + guarded writeback via smem staging epilogue.
#define AS_STRIDE 36
#define BS_STRIDE 132
#define AS_TILE (128 * AS_STRIDE)
#define BS_TILE (32 * BS_STRIDE)
#define GEMM_SMEM_BYTES ((2 * AS_TILE + 2 * BS_TILE) * 4)

__device__ __forceinline__ unsigned smem_u32(const void* p) {
    return (unsigned)__cvta_generic_to_shared(p);
}

template <int RELU>
__global__ __launch_bounds__(256) void gemm_tf32(
    const float* __restrict__ A, const float* __restrict__ W,
    const float* __restrict__ bias, float* __restrict__ Cout,
    int M, int K, int N) {
    extern __shared__ float smem[];
    float* As = smem;                 // [2][128][36]
    float* Bs = smem + 2 * AS_TILE;   // [2][32][132]
    float* stage = smem;              // reused for epilogue [128][132]

    const int tid = threadIdx.x;
    const int warp = tid >> 5;
    const int bm = blockIdx.y * 128;
    const int bn = blockIdx.x * 128;
    const int wm = (warp & 3) * 32;   // warp row start in tile
    const int wn = (warp >> 2) * 64;  // warp col start in tile

    wmma::fragment<wmma::accumulator, 16, 16, 8, float> acc[2][4];
#pragma unroll
    for (int mi = 0; mi < 2; mi++)
#pragma unroll
        for (int ni = 0; ni < 4; ni++) wmma::fill_fragment(acc[mi][ni], 0.0f);

    const int a_c4 = tid & 7;    // float4 col in A tile (8 per row)
    const int a_r  = tid >> 3;   // 0..31; rows a_r + i*32
    const int b_c4 = tid & 31;   // float4 col in B tile (32 per row)
    const int b_r  = tid >> 5;   // 0..7; rows b_r + i*8

    const int KT = K >> 5;

#define LOAD_TILE(buf, k0)                                                          \
    {                                                                               \
        _Pragma("unroll")                                                           \
        for (int i = 0; i < 4; i++) {                                               \
            int r = a_r + i * 32;                                                   \
            int gm = bm + r;                                                        \
            int gmc = gm < M ? gm : 0;                                              \
            const float* srcp = A + (size_t)gmc * K + (k0) + a_c4 * 4;              \
            int sz = gm < M ? 16 : 0;                                               \
            unsigned dst = smem_u32(&As[(buf) * AS_TILE + r * AS_STRIDE + a_c4 * 4]); \
            asm volatile("cp.async.cg.shared.global [%0], [%1], 16, %2;\n"          \
                         :: "r"(dst), "l"(srcp), "r"(sz));                           \
        }                                                                           \
        _Pragma("unroll")                                                           \
        for (int i = 0; i < 4; i++) {                                               \
            int r = b_r + i * 8;                                                    \
            const float* srcp = W + (size_t)((k0) + r) * N + bn + b_c4 * 4;         \
            unsigned dst = smem_u32(&Bs[(buf) * BS_TILE + r * BS_STRIDE + b_c4 * 4]); \
            asm volatile("cp.async.cg.shared.global [%0], [%1], 16, 16;\n"          \
                         :: "r"(dst), "l"(srcp));                                    \
        }                                                                           \
        asm volatile("cp.async.commit_group;\n");                                  \
    }

    LOAD_TILE(0, 0);

    for (int kt = 0; kt < KT; kt++) {
        asm volatile("cp.async.wait_group 0;\n");
        __syncthreads();
        if (kt + 1 < KT) LOAD_TILE((kt + 1) & 1, (kt + 1) << 5);

        const float* Ab = &As[(kt & 1) * AS_TILE];
        const float* Bb = &Bs[(kt & 1) * BS_TILE];
#pragma unroll
        for (int kk = 0; kk < 4; kk++) {
            wmma::fragment<wmma::matrix_a, 16, 16, 8, wmma::precision::tf32, wmma::row_major> af[2];
            wmma::fragment<wmma::matrix_b, 16, 16, 8, wmma::precision::tf32, wmma::row_major> bf[4];
#pragma unroll
            for (int mi = 0; mi < 2; mi++) {
                wmma::load_matrix_sync(af[mi], Ab + (wm + mi * 16) * AS_STRIDE + kk * 8, AS_STRIDE);
#pragma unroll
                for (int t = 0; t < af[mi].num_elements; t++)
                    af[mi].x[t] = wmma::__float_to_tf32(af[mi].x[t]);
            }
#pragma unroll
            for (int ni = 0; ni < 4; ni++) {
                wmma::load_matrix_sync(bf[ni], Bb + (kk * 8) * BS_STRIDE + wn + ni * 16, BS_STRIDE);
#pragma unroll
                for (int t = 0; t < bf[ni].num_elements; t++)
                    bf[ni].x[t] = wmma::__float_to_tf32(bf[ni].x[t]);
            }
#pragma unroll
            for (int mi = 0; mi < 2; mi++)
#pragma unroll
                for (int ni = 0; ni < 4; ni++)
                    wmma::mma_sync(acc[mi][ni], af[mi], bf[ni], acc[mi][ni]);
        }
    }

    // epilogue: stage accumulators in smem (layout-agnostic), then biased writeback
    __syncthreads();
#pragma unroll
    for (int mi = 0; mi < 2; mi++)
#pragma unroll
        for (int ni = 0; ni < 4; ni++)
            wmma::store_matrix_sync(stage + (wm + mi * 16) * BS_STRIDE + wn + ni * 16,
                                    acc[mi][ni], BS_STRIDE, wmma::mem_row_major);
    __syncthreads();

    const int wr = tid >> 5;        // 0..7
    const int wc = (tid & 31) * 4;  // 0..124
#pragma unroll
    for (int i = 0; i < 16; i++) {
        int r = wr + i * 8;
        int gm = bm + r;
        if (gm < M) {
            float4 v = *(float4*)&stage[r * BS_STRIDE + wc];
            int gn = bn + wc;
            v.x += __ldg(bias + gn + 0);
            v.y += __ldg(bias + gn + 1);
            v.z += __ldg(bias + gn + 2);
            v.w += __ldg(bias + gn + 3);
            if (RELU) {
                v.x = fmaxf(v.x, 0.f); v.y = fmaxf(v.y, 0.f);
                v.z = fmaxf(v.z, 0.f); v.w = fmaxf(v.w, 0.f);
            }
            *(float4*)(Cout + (size_t)gm * N + gn) = v;
        }
    }
#undef LOAD_TILE
}

// ---------------- residual + LayerNorm: out = LN(resid + delta) -------------
__global__ void ln_kernel(const float* __restrict__ resid, const float* __restrict__ delta,
                          const float* __restrict__ gamma, const float* __restrict__ beta,
                          float* __restrict__ out, int Mrows) {
    int warp = threadIdx.x >> 5;
    int lane = threadIdx.x & 31;
    int row = blockIdx.x * 8 + warp;
    if (row >= Mrows) return;
    const float* r = resid + (size_t)row * CDIM;
    const float* d = delta + (size_t)row * CDIM;
    float v[8];
    float s = 0.f;
#pragma unroll
    for (int i = 0; i < 8; i++) {
        int c = lane + i * 32;
        v[i] = r[c] + d[c];
        s += v[i];
    }
#pragma unroll
    for (int o = 16; o > 0; o >>= 1) s += __shfl_xor_sync(0xffffffffu, s, o);
    float mean = s * (1.0f / 256.0f);
    float vs = 0.f;
#pragma unroll
    for (int i = 0; i < 8; i++) {
        float t = v[i] - mean;
        vs += t * t;
    }
#pragma unroll
    for (int o = 16; o > 0; o >>= 1) vs += __shfl_xor_sync(0xffffffffu, vs, o);
    float inv = rsqrtf(vs * (1.0f / 256.0f) + 1e-5f);
    float* op = out + (size_t)row * CDIM;
#pragma unroll
    for (int i = 0; i < 8; i++) {
        int c = lane + i * 32;
        op[c] = (v[i] - mean) * inv * gamma[c] + beta[c];
    }
}

// ---------------- MS deformable attention sampling --------------------------
__global__ void msda_kernel(const float* __restrict__ val, const float* __restrict__ off,
                            const float* __restrict__ attl, float* __restrict__ out) {
    int gw = blockIdx.x * 8 + (threadIdx.x >> 5);
    int lane = threadIdx.x & 31;
    if (gw >= BSZ * STOT * NHEAD) return;
    int h = gw % NHEAD;
    int bs = gw / NHEAD;       // b*S + s
    int s = bs % STOT;
    int b = bs / STOT;

    int rl;
    if (s < 15200) rl = 0;
    else if (s < 19000) rl = 1;
    else if (s < 19950) rl = 2;
    else rl = 3;
    int rs = s - c_start[rl];
    int rW = c_W[rl];
    float refx = ((rs % rW) + 0.5f) / (float)rW;
    float refy = ((rs / rW) + 0.5f) / (float)c_H[rl];

    const float* ap = attl + (size_t)bs * 128 + h * 16;
    float w[16];
    float mx = -1e30f;
#pragma unroll
    for (int i = 0; i < 16; i++) {
        w[i] = __ldg(ap + i);
        mx = fmaxf(mx, w[i]);
    }
    float ssum = 0.f;
#pragma unroll
    for (int i = 0; i < 16; i++) {
        w[i] = __expf(w[i] - mx);
        ssum += w[i];
    }
    float sinv = 1.0f / ssum;

    const float* op = off + (size_t)bs * 256 + h * 32;
    float acc = 0.f;
#pragma unroll
    for (int l = 0; l < NLVL; l++) {
        const int Hl = c_H[l], Wl = c_W[l];
        const float* vbase = val + ((size_t)b * STOT + c_start[l]) * CDIM + h * HDIM + lane;
#pragma unroll
        for (int p = 0; p < NPNT; p++) {
            float ox = __ldg(op + (l * 4 + p) * 2 + 0);
            float oy = __ldg(op + (l * 4 + p) * 2 + 1);
            float lx = refx * (float)Wl + ox - 0.5f;
            float ly = refy * (float)Hl + oy - 0.5f;
            float x0f = floorf(lx), y0f = floorf(ly);
            float fx = lx - x0f, fy = ly - y0f;
            int x0 = (int)x0f, y0 = (int)y0f;
            float aw = w[l * 4 + p] * sinv;
#pragma unroll
            for (int dy = 0; dy < 2; dy++) {
#pragma unroll
                for (int dx = 0; dx < 2; dx++) {
                    int xi = x0 + dx, yi = y0 + dy;
                    if (xi >= 0 && xi < Wl && yi >= 0 && yi < Hl) {
                        float cw = (dx ? fx : 1.f - fx) * (dy ? fy : 1.f - fy) * aw;
                        acc += __ldg(vbase + (size_t)(yi * Wl + xi) * CDIM) * cw;
                    }
                }
            }
        }
    }
    out[(size_t)bs * CDIM + h * HDIM + lane] = acc;
}

// ---------------- host orchestration ----------------------------------------
extern "C" void kernel_launch(void* const* d_in, const int* in_sizes, int n_in,
                              void* d_out, int out_size) {
    const float* src  = (const float*)d_in[0];
    const float* pos  = (const float*)d_in[1];
    const float* Woff = (const float*)d_in[2];
    const float* boff = (const float*)d_in[3];
    const float* Watt = (const float*)d_in[4];
    const float* batt = (const float*)d_in[5];
    const float* Wval = (const float*)d_in[6];
    const float* bval = (const float*)d_in[7];
    const float* Wout = (const float*)d_in[8];
    const float* bout = (const float*)d_in[9];
    const float* W1   = (const float*)d_in[10];
    const float* b1   = (const float*)d_in[11];
    const float* W2   = (const float*)d_in[12];
    const float* b2   = (const float*)d_in[13];
    const float* g1   = (const float*)d_in[14];
    const float* be1  = (const float*)d_in[15];
    const float* g2   = (const float*)d_in[16];
    const float* be2  = (const float*)d_in[17];

    float *qp, *valp, *offp, *attp, *sampp, *projp, *xap, *ffp, *gxp;
    cudaGetSymbolAddress((void**)&qp, g_q);
    cudaGetSymbolAddress((void**)&valp, g_val);
    cudaGetSymbolAddress((void**)&offp, g_off);
    cudaGetSymbolAddress((void**)&attp, g_att);
    cudaGetSymbolAddress((void**)&sampp, g_samp);
    cudaGetSymbolAddress((void**)&projp, g_proj);
    cudaGetSymbolAddress((void**)&xap, g_xa);
    cudaGetSymbolAddress((void**)&ffp, g_ff);
    cudaGetSymbolAddress((void**)&gxp, g_x);

    cudaFuncSetAttribute(gemm_tf32<0>, cudaFuncAttributeMaxDynamicSharedMemorySize, GEMM_SMEM_BYTES);
    cudaFuncSetAttribute(gemm_tf32<1>, cudaFuncAttributeMaxDynamicSharedMemorySize, GEMM_SMEM_BYTES);

    const int M = MTOT;
    const int gy = (M + 127) / 128;          // 316
    const int lnBlocks = (M + 7) / 8;        // 5050
    const int addN4 = M * CDIM / 4;
    const int addBlocks = (addN4 + 255) / 256;
    const int msdaBlocks = (BSZ * STOT * NHEAD + 7) / 8;  // 40394

    const float* x = src;
    for (int l = 0; l < NLAYER; l++) {
        const float* Woff_l = Woff + (size_t)l * CDIM * 256;
        const float* boff_l = boff + (size_t)l * 256;
        const float* Watt_l = Watt + (size_t)l * CDIM * 128;
        const float* batt_l = batt + (size_t)l * 128;
        const float* Wval_l = Wval + (size_t)l * CDIM * CDIM;
        const float* bval_l = bval + (size_t)l * CDIM;
        const float* Wout_l = Wout + (size_t)l * CDIM * CDIM;
        const float* bout_l = bout + (size_t)l * CDIM;
        const float* W1_l = W1 + (size_t)l * CDIM * DFFD;
        const float* b1_l = b1 + (size_t)l * DFFD;
        const float* W2_l = W2 + (size_t)l * DFFD * CDIM;
        const float* b2_l = b2 + (size_t)l * CDIM;
        const float* g1_l = g1 + (size_t)l * CDIM;
        const float* be1_l = be1 + (size_t)l * CDIM;
        const float* g2_l = g2 + (size_t)l * CDIM;
        const float* be2_l = be2 + (size_t)l * CDIM;

        // q = x + pos
        add_kernel<<<addBlocks, 256>>>(x, pos, qp, addN4);
        // value / offsets / attention logits
        gemm_tf32<0><<<dim3(2, gy), 256, GEMM_SMEM_BYTES>>>(x, Wval_l, bval_l, valp, M, 256, 256);
        gemm_tf32<0><<<dim3(2, gy), 256, GEMM_SMEM_BYTES>>>(qp, Woff_l, boff_l, offp, M, 256, 256);
        gemm_tf32<0><<<dim3(1, gy), 256, GEMM_SMEM_BYTES>>>(qp, Watt_l, batt_l, attp, M, 256, 128);
        // deformable sampling (softmax fused)
        msda_kernel<<<msdaBlocks, 256>>>(valp, offp, attp, sampp);
        // output projection
        gemm_tf32<0><<<dim3(2, gy), 256, GEMM_SMEM_BYTES>>>(sampp, Wout_l, bout_l, projp, M, 256, 256);
        // x1 = LN(x + proj)
        ln_kernel<<<lnBlocks, 256>>>(x, projp, g1_l, be1_l, xap, M);
        // FFN
        gemm_tf32<1><<<dim3(8, gy), 256, GEMM_SMEM_BYTES>>>(xap, W1_l, b1_l, ffp, M, 256, 1024);
        gemm_tf32<0><<<dim3(2, gy), 256, GEMM_SMEM_BYTES>>>(ffp, W2_l, b2_l, projp, M, 1024, 256);
        // x = LN(x1 + ff)
        float* xout = (l == NLAYER - 1) ? (float*)d_out : gxp;
        ln_kernel<<<lnBlocks, 256>>>(xap, projp, g2_l, be2_l, xout, M);
        x = gxp;
    }
}